// round 8
// baseline (speedup 1.0000x reference)
#include <cuda_runtime.h>
#include <cuda_bf16.h>
#include <cstdint>

// Problem constants
#define NB   32
#define CIN  256
#define HH   96
#define WW   96
#define CM   64
#define PP   256
#define HW   (HH*WW)          // 9216
#define KK   3

// Scratch (static device globals -- no runtime allocation)
__device__ float g_f[(size_t)NB * CM * HW];     // 75.5 MB intermediate f
__device__ float g_xp[NB * CIN * 9];            // pooled x
__device__ float g_g[NB * CM * 9];              // dynamic depthwise filters

// ---------------------------------------------------------------------------
// Kernel 1: adaptive avg pool 96x96 -> 3x3 (exact 32x32 block mean)
// grid = N*C blocks, 96 threads (thread = column w; warp = px)
// ---------------------------------------------------------------------------
__global__ void pool_kernel(const float* __restrict__ x) {
    int nc = blockIdx.x;
    int w  = threadIdx.x;            // 0..95
    const float* xb = x + (size_t)nc * HW;
    float s0 = 0.f, s1 = 0.f, s2 = 0.f;
    #pragma unroll 8
    for (int h = 0; h < 32; h++)  s0 += xb[h * WW + w];
    #pragma unroll 8
    for (int h = 32; h < 64; h++) s1 += xb[h * WW + w];
    #pragma unroll 8
    for (int h = 64; h < 96; h++) s2 += xb[h * WW + w];
    #pragma unroll
    for (int off = 16; off > 0; off >>= 1) {
        s0 += __shfl_down_sync(0xffffffff, s0, off);
        s1 += __shfl_down_sync(0xffffffff, s1, off);
        s2 += __shfl_down_sync(0xffffffff, s2, off);
    }
    if ((w & 31) == 0) {
        int px = w >> 5;
        const float inv = 1.0f / 1024.0f;
        g_xp[nc * 9 + 0 * 3 + px] = s0 * inv;
        g_xp[nc * 9 + 1 * 3 + px] = s1 * inv;
        g_xp[nc * 9 + 2 * 3 + px] = s2 * inv;
    }
}

// ---------------------------------------------------------------------------
// Kernel 2: g[n][cm][k] = conv_b[cm] + sum_c conv_w[cm][c] * xp[n][c][k]
// grid = (9, N), 64 threads (thread = cm); float4 reads of conv_w row
// ---------------------------------------------------------------------------
__global__ void gfilt_kernel(const float* __restrict__ conv_w,
                             const float* __restrict__ conv_b) {
    int k  = blockIdx.x;   // 0..8
    int n  = blockIdx.y;
    int cm = threadIdx.x;  // 0..63
    float acc = conv_b[cm];
    const float*  xpb = g_xp + (size_t)n * CIN * 9 + k;
    const float4* wb4 = (const float4*)(conv_w + (size_t)cm * CIN);
    #pragma unroll 4
    for (int c4 = 0; c4 < CIN / 4; c4++) {
        float4 wv = wb4[c4];
        int c = c4 * 4;
        acc += xpb[(c + 0) * 9] * wv.x + xpb[(c + 1) * 9] * wv.y
             + xpb[(c + 2) * 9] * wv.z + xpb[(c + 3) * 9] * wv.w;
    }
    g_g[((size_t)n * CM + cm) * 9 + k] = acc;
}

// ---------------------------------------------------------------------------
// Kernel 3: f = relu(W1 @ x + b1)  -- GEMM 64 x 9216 per sample, K=256
// grid = (36, N) : 256-pixel tiles. 256 threads, 8x8 register tile per thread.
// smem: w_s [256][68] padded transpose of W1 (69632B), x_s [32][256] (32768B)
// ---------------------------------------------------------------------------
#define K3_WS 68
__global__ __launch_bounds__(256, 2)
void f_kernel(const float* __restrict__ x, const float* __restrict__ conv_w,
              const float* __restrict__ conv_b) {
    extern __shared__ float sm[];
    float* w_s = sm;                 // [256][68]
    float* x_s = sm + 256 * K3_WS;   // [32][256]

    int tid = threadIdx.x;
    int n = blockIdx.y;
    int pbase = blockIdx.x * 256;

    // Stage W1 transposed (k-major): w_s[c*68 + cm] = conv_w[cm*256 + c]
    // float4 global reads (4 consecutive c for one cm), scattered smem stores.
    for (int i = tid; i < (CM * CIN) / 4; i += 256) {
        int idx = i * 4;
        int cm = idx >> 8, c = idx & 255;      // c is a multiple of 4
        float4 wv = *(const float4*)(conv_w + idx);
        w_s[(c + 0) * K3_WS + cm] = wv.x;
        w_s[(c + 1) * K3_WS + cm] = wv.y;
        w_s[(c + 2) * K3_WS + cm] = wv.z;
        w_s[(c + 3) * K3_WS + cm] = wv.w;
    }

    float acc[8][8];
    #pragma unroll
    for (int r = 0; r < 8; r++)
        #pragma unroll
        for (int j = 0; j < 8; j++) acc[r][j] = 0.f;

    int og = tid >> 5;   // 0..7  -> cm group of 8
    int pg = tid & 31;   // 0..31 -> pixel group of 8

    const float* xn = x + (size_t)n * CIN * HW + pbase;

    for (int c0 = 0; c0 < CIN; c0 += 32) {
        __syncthreads();
        // stage 32 channels x 256 pixels (coalesced float4)
        for (int i = tid; i < 2048; i += 256) {
            int ch = i >> 6, f4 = i & 63;
            float4 v = *(const float4*)(xn + (size_t)(c0 + ch) * HW + f4 * 4);
            *(float4*)(x_s + ch * 256 + f4 * 4) = v;
        }
        __syncthreads();
        #pragma unroll
        for (int kc = 0; kc < 32; kc++) {
            int c = c0 + kc;
            float4 wa  = *(const float4*)(w_s + c * K3_WS + og * 8);
            float4 wb4 = *(const float4*)(w_s + c * K3_WS + og * 8 + 4);
            float4 xa  = *(const float4*)(x_s + kc * 256 + pg * 8);
            float4 xb4 = *(const float4*)(x_s + kc * 256 + pg * 8 + 4);
            float wr[8] = {wa.x, wa.y, wa.z, wa.w, wb4.x, wb4.y, wb4.z, wb4.w};
            float xv[8] = {xa.x, xa.y, xa.z, xa.w, xb4.x, xb4.y, xb4.z, xb4.w};
            #pragma unroll
            for (int r = 0; r < 8; r++)
                #pragma unroll
                for (int j = 0; j < 8; j++)
                    acc[r][j] += wr[r] * xv[j];
        }
    }

    // epilogue: bias + relu, vectorized store
    int cmb = og * 8;
    float* fb = g_f + (size_t)n * CM * HW + pbase + pg * 8;
    #pragma unroll
    for (int r = 0; r < 8; r++) {
        float b = conv_b[cmb + r];
        float4 o0, o1;
        o0.x = fmaxf(acc[r][0] + b, 0.f); o0.y = fmaxf(acc[r][1] + b, 0.f);
        o0.z = fmaxf(acc[r][2] + b, 0.f); o0.w = fmaxf(acc[r][3] + b, 0.f);
        o1.x = fmaxf(acc[r][4] + b, 0.f); o1.y = fmaxf(acc[r][5] + b, 0.f);
        o1.z = fmaxf(acc[r][6] + b, 0.f); o1.w = fmaxf(acc[r][7] + b, 0.f);
        float* fo = fb + (size_t)(cmb + r) * HW;
        *(float4*)(fo)     = o0;
        *(float4*)(fo + 4) = o1;
    }
}

// ---------------------------------------------------------------------------
// Kernel 4: o = depthwise3x3(f, g) + dw_b ; y = fuse_w @ o + fuse_b
// grid = (48, N) : 2-row tiles. 256 threads.
// smem phase A: f_s [64 cm][4 rows][104] (halo+pad, zero-filled)    106496 B
//       phase B: w2  [64 k][260]   (fuse_w transposed, aliases f_s)
//       o_s [64][192]                                                49152 B
// ---------------------------------------------------------------------------
#define K4_FW   104
#define K4_FSZ  (CM * 4 * K4_FW)    // 26624 floats
#define K4_W2S  260
__global__ __launch_bounds__(256, 1)
void dwfuse_kernel(const float* __restrict__ dw_b,
                   const float* __restrict__ fuse_w,
                   const float* __restrict__ fuse_b,
                   float* __restrict__ y) {
    extern __shared__ float sm[];
    float* f_s = sm;                // phase A
    float* o_s = sm + K4_FSZ;       // [64][192]

    int tid = threadIdx.x;
    int n  = blockIdx.y;
    int ht = blockIdx.x;
    int h0 = ht * 2;

    // Hoisted depthwise operand loads: issue global reads BEFORE the f_s
    // staging barrier so their latency overlaps the smem fill (1 CTA/SM ->
    // no cross-CTA hiding; this sits on the critical path of every block).
    int pair = tid >> 1, half = tid & 1;
    int dcm = pair >> 1, dty = pair & 1;
    float gg[9];
    {
        const float* gp = g_g + ((size_t)n * CM + dcm) * 9;
        #pragma unroll
        for (int k = 0; k < 9; k++) gg[k] = gp[k];
    }
    float db = dw_b[dcm];

    // zero f_s (covers halo padding + out-of-range rows)
    for (int i = tid; i < K4_FSZ / 4; i += 256)
        *(float4*)(f_s + i * 4) = make_float4(0.f, 0.f, 0.f, 0.f);
    __syncthreads();

    // load f rows h0-1 .. h0+2 for all 64 cm
    const float* fn = g_f + (size_t)n * CM * HW;
    for (int i = tid; i < 6144; i += 256) {       // 64 cm * 4 rows * 24 float4
        int cm = i / 96;
        int rem = i % 96;
        int r = rem / 24, q = rem % 24;
        int h = h0 - 1 + r;
        if (h >= 0 && h < HH) {
            float4 v = *(const float4*)(fn + (size_t)cm * HW + h * WW + q * 4);
            *(float4*)(f_s + cm * (4 * K4_FW) + r * K4_FW + 4 + q * 4) = v;
        }
    }
    __syncthreads();

    // dynamic depthwise 3x3: thread = (cm, ty, half-row of 48)
    {
        const float* fr = f_s + dcm * (4 * K4_FW) + dty * K4_FW;
        int w0 = half * 48;
        #pragma unroll 6
        for (int w = w0; w < w0 + 48; w++) {
            float s = db;
            s += gg[0] * fr[w + 3]              + gg[1] * fr[w + 4]              + gg[2] * fr[w + 5];
            s += gg[3] * fr[K4_FW + w + 3]      + gg[4] * fr[K4_FW + w + 4]      + gg[5] * fr[K4_FW + w + 5];
            s += gg[6] * fr[2 * K4_FW + w + 3]  + gg[7] * fr[2 * K4_FW + w + 4]  + gg[8] * fr[2 * K4_FW + w + 5];
            o_s[dcm * 192 + dty * 96 + w] = s;
        }
    }
    __syncthreads();

    // stage fuse_w transposed (k-major) into the f_s buffer: w2[cm*260 + p]
    float* w2 = f_s;
    for (int i = tid; i < PP * CM; i += 256) {
        int p = i >> 6, cm = i & 63;
        w2[cm * K4_W2S + p] = fuse_w[i];
    }
    __syncthreads();

    // fuse GEMM: 256 outs x 192 pixels, 3 iterations of 256x64 block tiles
    int og = tid >> 3;   // 0..31 -> p group of 8
    int pg = tid & 7;    // 0..7  -> pixel group of 8
    float fb8[8];
    #pragma unroll
    for (int r = 0; r < 8; r++) fb8[r] = fuse_b[og * 8 + r];

    float* yn = y + (size_t)n * PP * HW + h0 * WW;

    for (int iter = 0; iter < 3; iter++) {
        int pb = iter * 64;
        float acc[8][8];
        #pragma unroll
        for (int r = 0; r < 8; r++)
            #pragma unroll
            for (int j = 0; j < 8; j++) acc[r][j] = 0.f;

        #pragma unroll 8
        for (int k = 0; k < CM; k++) {
            float4 wa  = *(const float4*)(w2 + k * K4_W2S + og * 8);
            float4 wb4 = *(const float4*)(w2 + k * K4_W2S + og * 8 + 4);
            float4 oa  = *(const float4*)(o_s + k * 192 + pb + pg * 8);
            float4 ob  = *(const float4*)(o_s + k * 192 + pb + pg * 8 + 4);
            float wr[8] = {wa.x, wa.y, wa.z, wa.w, wb4.x, wb4.y, wb4.z, wb4.w};
            float ov[8] = {oa.x, oa.y, oa.z, oa.w, ob.x, ob.y, ob.z, ob.w};
            #pragma unroll
            for (int r = 0; r < 8; r++)
                #pragma unroll
                for (int j = 0; j < 8; j++)
                    acc[r][j] += wr[r] * ov[j];
        }

        int l0 = pb + pg * 8;   // pixel offset within the 192-pixel tile
        #pragma unroll
        for (int r = 0; r < 8; r++) {
            float b = fb8[r];
            float4 v0, v1;
            v0.x = acc[r][0] + b; v0.y = acc[r][1] + b;
            v0.z = acc[r][2] + b; v0.w = acc[r][3] + b;
            v1.x = acc[r][4] + b; v1.y = acc[r][5] + b;
            v1.z = acc[r][6] + b; v1.w = acc[r][7] + b;
            float* yo = yn + (size_t)(og * 8 + r) * HW + l0;
            *(float4*)(yo)     = v0;
            *(float4*)(yo + 4) = v1;
        }
    }
}

// ---------------------------------------------------------------------------
extern "C" void kernel_launch(void* const* d_in, const int* in_sizes, int n_in,
                              void* d_out, int out_size) {
    const float* x      = (const float*)d_in[0];
    const float* conv_w = (const float*)d_in[1];
    const float* conv_b = (const float*)d_in[2];
    const float* dw_b   = (const float*)d_in[3];
    const float* fuse_w = (const float*)d_in[4];
    const float* fuse_b = (const float*)d_in[5];
    float* y = (float*)d_out;

    // Idempotent host-side attribute sets -- unconditional every call
    // (no static guards; identical work on every invocation).
    size_t smem3 = (256 * K3_WS + 32 * 256) * sizeof(float);        // 102400 B
    size_t smem4 = (K4_FSZ + CM * 192) * sizeof(float);             // 155648 B
    cudaFuncSetAttribute(f_kernel, cudaFuncAttributeMaxDynamicSharedMemorySize, (int)smem3);
    cudaFuncSetAttribute(dwfuse_kernel, cudaFuncAttributeMaxDynamicSharedMemorySize, (int)smem4);

    pool_kernel<<<NB * CIN, 96>>>(x);
    gfilt_kernel<<<dim3(9, NB), CM>>>(conv_w, conv_b);
    f_kernel<<<dim3(36, NB), 256, smem3>>>(x, conv_w, conv_b);
    dwfuse_kernel<<<dim3(48, NB), 256, smem4>>>(dw_b, fuse_w, fuse_b, y);
}

// round 10
// speedup vs baseline: 1.1510x; 1.1510x over previous
#include <cuda_runtime.h>
#include <cuda_bf16.h>
#include <cstdint>

// Problem constants
#define NB   32
#define CIN  256
#define HH   96
#define WW   96
#define CM   64
#define PP   256
#define HW   (HH*WW)          // 9216
#define KK   3

typedef unsigned long long ull;

// Scratch (static device globals -- no runtime allocation)
__device__ float g_f[(size_t)NB * CM * HW];     // 75.5 MB intermediate f
__device__ float g_xp[NB * CIN * 9];            // pooled x
__device__ float g_g[NB * CM * 9];              // dynamic depthwise filters

// ---- packed fp32x2 helpers (sm_103a FFMA2: 2 exact fp32 FMAs per instr) ----
__device__ __forceinline__ ull pack2(float lo, float hi) {
    ull r;
    asm("mov.b64 %0, {%1, %2};" : "=l"(r) : "f"(lo), "f"(hi));
    return r;
}
__device__ __forceinline__ void fma2(ull& d, ull a, ull b) {
    asm("fma.rn.f32x2 %0, %1, %2, %0;" : "+l"(d) : "l"(a), "l"(b));
}
__device__ __forceinline__ float2 unpack2(ull v) {
    float2 f;
    asm("mov.b64 {%0, %1}, %2;" : "=f"(f.x), "=f"(f.y) : "l"(v));
    return f;
}

// ---------------------------------------------------------------------------
// Kernel 1: adaptive avg pool 96x96 -> 3x3 (exact 32x32 block mean)
// ---------------------------------------------------------------------------
__global__ void pool_kernel(const float* __restrict__ x) {
    int nc = blockIdx.x;
    int w  = threadIdx.x;            // 0..95
    const float* xb = x + (size_t)nc * HW;
    float s0 = 0.f, s1 = 0.f, s2 = 0.f;
    #pragma unroll 8
    for (int h = 0; h < 32; h++)  s0 += xb[h * WW + w];
    #pragma unroll 8
    for (int h = 32; h < 64; h++) s1 += xb[h * WW + w];
    #pragma unroll 8
    for (int h = 64; h < 96; h++) s2 += xb[h * WW + w];
    #pragma unroll
    for (int off = 16; off > 0; off >>= 1) {
        s0 += __shfl_down_sync(0xffffffff, s0, off);
        s1 += __shfl_down_sync(0xffffffff, s1, off);
        s2 += __shfl_down_sync(0xffffffff, s2, off);
    }
    if ((w & 31) == 0) {
        int px = w >> 5;
        const float inv = 1.0f / 1024.0f;
        g_xp[nc * 9 + 0 * 3 + px] = s0 * inv;
        g_xp[nc * 9 + 1 * 3 + px] = s1 * inv;
        g_xp[nc * 9 + 2 * 3 + px] = s2 * inv;
    }
}

// ---------------------------------------------------------------------------
// Kernel 2: g[n][cm][k] = conv_b[cm] + sum_c conv_w[cm][c] * xp[n][c][k]
// ---------------------------------------------------------------------------
__global__ void gfilt_kernel(const float* __restrict__ conv_w,
                             const float* __restrict__ conv_b) {
    int k  = blockIdx.x;   // 0..8
    int n  = blockIdx.y;
    int cm = threadIdx.x;  // 0..63
    float acc = conv_b[cm];
    const float*  xpb = g_xp + (size_t)n * CIN * 9 + k;
    const float4* wb4 = (const float4*)(conv_w + (size_t)cm * CIN);
    #pragma unroll 4
    for (int c4 = 0; c4 < CIN / 4; c4++) {
        float4 wv = wb4[c4];
        int c = c4 * 4;
        acc += xpb[(c + 0) * 9] * wv.x + xpb[(c + 1) * 9] * wv.y
             + xpb[(c + 2) * 9] * wv.z + xpb[(c + 3) * 9] * wv.w;
    }
    g_g[((size_t)n * CM + cm) * 9 + k] = acc;
}

// ---------------------------------------------------------------------------
// Kernel 3: f = relu(W1 @ x + b1) -- GEMM 64 x 9216 per sample, K=256
// 8x8 register tile per thread, accumulators packed as 8x4 f32x2 pairs.
// ---------------------------------------------------------------------------
#define K3_WS 68
__global__ __launch_bounds__(256, 2)
void f_kernel(const float* __restrict__ x, const float* __restrict__ conv_w,
              const float* __restrict__ conv_b) {
    extern __shared__ float sm[];
    float* w_s = sm;                 // [256][68]
    float* x_s = sm + 256 * K3_WS;   // [32][256]

    int tid = threadIdx.x;
    int n = blockIdx.y;
    int pbase = blockIdx.x * 256;

    // Stage W1 transposed (k-major), float4 global reads
    for (int i = tid; i < (CM * CIN) / 4; i += 256) {
        int idx = i * 4;
        int cm = idx >> 8, c = idx & 255;
        float4 wv = *(const float4*)(conv_w + idx);
        w_s[(c + 0) * K3_WS + cm] = wv.x;
        w_s[(c + 1) * K3_WS + cm] = wv.y;
        w_s[(c + 2) * K3_WS + cm] = wv.z;
        w_s[(c + 3) * K3_WS + cm] = wv.w;
    }

    ull acc2[8][4];
    #pragma unroll
    for (int r = 0; r < 8; r++)
        #pragma unroll
        for (int j = 0; j < 4; j++) acc2[r][j] = 0ULL;

    int og = tid >> 5;   // 0..7  -> cm group of 8 (constant per warp)
    int pg = tid & 31;   // 0..31 -> pixel group of 8

    const float* xn = x + (size_t)n * CIN * HW + pbase;

    for (int c0 = 0; c0 < CIN; c0 += 32) {
        __syncthreads();
        for (int i = tid; i < 2048; i += 256) {
            int ch = i >> 6, f4 = i & 63;
            float4 v = *(const float4*)(xn + (size_t)(c0 + ch) * HW + f4 * 4);
            *(float4*)(x_s + ch * 256 + f4 * 4) = v;
        }
        __syncthreads();
        #pragma unroll
        for (int kc = 0; kc < 32; kc++) {
            int c = c0 + kc;
            float4 wa  = *(const float4*)(w_s + c * K3_WS + og * 8);
            float4 wb4 = *(const float4*)(w_s + c * K3_WS + og * 8 + 4);
            ull wp[8];
            wp[0] = pack2(wa.x, wa.x);  wp[1] = pack2(wa.y, wa.y);
            wp[2] = pack2(wa.z, wa.z);  wp[3] = pack2(wa.w, wa.w);
            wp[4] = pack2(wb4.x, wb4.x); wp[5] = pack2(wb4.y, wb4.y);
            wp[6] = pack2(wb4.z, wb4.z); wp[7] = pack2(wb4.w, wb4.w);
            const ulonglong2* xv = (const ulonglong2*)(x_s + kc * 256 + pg * 8);
            ulonglong2 x01 = xv[0];
            ulonglong2 x23 = xv[1];
            #pragma unroll
            for (int r = 0; r < 8; r++) {
                fma2(acc2[r][0], wp[r], x01.x);
                fma2(acc2[r][1], wp[r], x01.y);
                fma2(acc2[r][2], wp[r], x23.x);
                fma2(acc2[r][3], wp[r], x23.y);
            }
        }
    }

    // epilogue: unpack + bias + relu, vectorized store
    int cmb = og * 8;
    float* fb = g_f + (size_t)n * CM * HW + pbase + pg * 8;
    #pragma unroll
    for (int r = 0; r < 8; r++) {
        float b = conv_b[cmb + r];
        float2 p0 = unpack2(acc2[r][0]);
        float2 p1 = unpack2(acc2[r][1]);
        float2 p2 = unpack2(acc2[r][2]);
        float2 p3 = unpack2(acc2[r][3]);
        float4 o0, o1;
        o0.x = fmaxf(p0.x + b, 0.f); o0.y = fmaxf(p0.y + b, 0.f);
        o0.z = fmaxf(p1.x + b, 0.f); o0.w = fmaxf(p1.y + b, 0.f);
        o1.x = fmaxf(p2.x + b, 0.f); o1.y = fmaxf(p2.y + b, 0.f);
        o1.z = fmaxf(p3.x + b, 0.f); o1.w = fmaxf(p3.y + b, 0.f);
        float* fo = fb + (size_t)(cmb + r) * HW;
        *(float4*)(fo)     = o0;
        *(float4*)(fo + 4) = o1;
    }
}

// ---------------------------------------------------------------------------
// Kernel 4: o = depthwise3x3(f, g) + dw_b ; y = fuse_w @ o + fuse_b
// grid = (48, N). 256 threads.
// Depthwise conflict-free: warp = 16 (cm,row) tasks, lanes span w (stride 3).
// Fuse GEMM in packed f32x2.
// ---------------------------------------------------------------------------
#define K4_FW   104
#define K4_FSZ  (CM * 4 * K4_FW)    // 26624 floats
#define K4_W2S  260
__global__ __launch_bounds__(256, 1)
void dwfuse_kernel(const float* __restrict__ dw_b,
                   const float* __restrict__ fuse_w,
                   const float* __restrict__ fuse_b,
                   float* __restrict__ y) {
    extern __shared__ float sm[];
    float* f_s   = sm;                       // phase A [64][4][104]
    float* o_s   = sm + K4_FSZ;              // [64][192]
    float* g_s   = sm + K4_FSZ + CM * 192;   // [64][9]
    float* dwb_s = g_s + CM * 9;             // [64]

    int tid = threadIdx.x;
    int n  = blockIdx.y;
    int ht = blockIdx.x;
    int h0 = ht * 2;

    // stage g filters + dw bias into smem (broadcast-read later)
    for (int i = tid; i < CM * 9; i += 256) g_s[i] = g_g[(size_t)n * CM * 9 + i];
    if (tid < CM) dwb_s[tid] = dw_b[tid];

    // zero f_s (covers halo padding + out-of-range rows)
    for (int i = tid; i < K4_FSZ / 4; i += 256)
        *(float4*)(f_s + i * 4) = make_float4(0.f, 0.f, 0.f, 0.f);
    __syncthreads();

    // load f rows h0-1 .. h0+2 for all 64 cm
    const float* fn = g_f + (size_t)n * CM * HW;
    for (int i = tid; i < 6144; i += 256) {       // 64 cm * 4 rows * 24 float4
        int cm = i / 96;
        int rem = i % 96;
        int r = rem / 24, q = rem % 24;
        int h = h0 - 1 + r;
        if (h >= 0 && h < HH) {
            float4 v = *(const float4*)(fn + (size_t)cm * HW + h * WW + q * 4);
            *(float4*)(f_s + cm * (4 * K4_FW) + r * K4_FW + 4 + q * 4) = v;
        }
    }
    __syncthreads();

    // dynamic depthwise 3x3, conflict-free: warp handles 16 (cm,ty) row-tasks,
    // lane covers pixels [lane*3, lane*3+2] via 5-value sliding window.
    {
        int wid = tid >> 5, lane = tid & 31;
        int px0 = lane * 3;
        #pragma unroll 4
        for (int t = 0; t < 16; t++) {
            int task = wid * 16 + t;
            int cm = task >> 1, ty = task & 1;
            const float* gq = g_s + cm * 9;
            const float* f0 = f_s + cm * (4 * K4_FW) + ty * K4_FW + px0 + 3;
            float db = dwb_s[cm];
            float s0 = db, s1 = db, s2 = db;
            #pragma unroll
            for (int r = 0; r < 3; r++) {
                const float* fr = f0 + r * K4_FW;
                float v0 = fr[0], v1 = fr[1], v2 = fr[2], v3 = fr[3], v4 = fr[4];
                float gr0 = gq[r * 3 + 0], gr1 = gq[r * 3 + 1], gr2 = gq[r * 3 + 2];
                s0 += gr0 * v0 + gr1 * v1 + gr2 * v2;
                s1 += gr0 * v1 + gr1 * v2 + gr2 * v3;
                s2 += gr0 * v2 + gr1 * v3 + gr2 * v4;
            }
            float* op = o_s + cm * 192 + ty * 96 + px0;
            op[0] = s0; op[1] = s1; op[2] = s2;
        }
    }
    __syncthreads();

    // stage fuse_w transposed (k-major) into the f_s buffer: w2[cm*260 + p]
    float* w2 = f_s;
    for (int i = tid; i < PP * CM; i += 256) {
        int p = i >> 6, cm = i & 63;
        w2[cm * K4_W2S + p] = fuse_w[i];
    }
    __syncthreads();

    // fuse GEMM: 256 outs x 192 pixels, packed f32x2, 3 tiles of 64 pixels
    int og = tid >> 3;   // 0..31 -> p group of 8
    int pg = tid & 7;    // 0..7  -> pixel group of 8
    float fb8[8];
    #pragma unroll
    for (int r = 0; r < 8; r++) fb8[r] = fuse_b[og * 8 + r];

    float* yn = y + (size_t)n * PP * HW + h0 * WW;

    for (int iter = 0; iter < 3; iter++) {
        int pb = iter * 64;
        ull acc2[8][4];
        #pragma unroll
        for (int r = 0; r < 8; r++)
            #pragma unroll
            for (int j = 0; j < 4; j++) acc2[r][j] = 0ULL;

        #pragma unroll 4
        for (int k = 0; k < CM; k++) {
            float4 wa  = *(const float4*)(w2 + k * K4_W2S + og * 8);
            float4 wb4 = *(const float4*)(w2 + k * K4_W2S + og * 8 + 4);
            ull wp[8];
            wp[0] = pack2(wa.x, wa.x);  wp[1] = pack2(wa.y, wa.y);
            wp[2] = pack2(wa.z, wa.z);  wp[3] = pack2(wa.w, wa.w);
            wp[4] = pack2(wb4.x, wb4.x); wp[5] = pack2(wb4.y, wb4.y);
            wp[6] = pack2(wb4.z, wb4.z); wp[7] = pack2(wb4.w, wb4.w);
            const ulonglong2* ov = (const ulonglong2*)(o_s + k * 192 + pb + pg * 8);
            ulonglong2 o01 = ov[0];
            ulonglong2 o23 = ov[1];
            #pragma unroll
            for (int r = 0; r < 8; r++) {
                fma2(acc2[r][0], wp[r], o01.x);
                fma2(acc2[r][1], wp[r], o01.y);
                fma2(acc2[r][2], wp[r], o23.x);
                fma2(acc2[r][3], wp[r], o23.y);
            }
        }

        int l0 = pb + pg * 8;
        #pragma unroll
        for (int r = 0; r < 8; r++) {
            float b = fb8[r];
            float2 p0 = unpack2(acc2[r][0]);
            float2 p1 = unpack2(acc2[r][1]);
            float2 p2 = unpack2(acc2[r][2]);
            float2 p3 = unpack2(acc2[r][3]);
            float4 v0, v1;
            v0.x = p0.x + b; v0.y = p0.y + b; v0.z = p1.x + b; v0.w = p1.y + b;
            v1.x = p2.x + b; v1.y = p2.y + b; v1.z = p3.x + b; v1.w = p3.y + b;
            float* yo = yn + (size_t)(og * 8 + r) * HW + l0;
            *(float4*)(yo)     = v0;
            *(float4*)(yo + 4) = v1;
        }
    }
}

// ---------------------------------------------------------------------------
extern "C" void kernel_launch(void* const* d_in, const int* in_sizes, int n_in,
                              void* d_out, int out_size) {
    const float* x      = (const float*)d_in[0];
    const float* conv_w = (const float*)d_in[1];
    const float* conv_b = (const float*)d_in[2];
    const float* dw_b   = (const float*)d_in[3];
    const float* fuse_w = (const float*)d_in[4];
    const float* fuse_b = (const float*)d_in[5];
    float* y = (float*)d_out;

    size_t smem3 = (256 * K3_WS + 32 * 256) * sizeof(float);              // 102400 B
    size_t smem4 = (K4_FSZ + CM * 192 + CM * 9 + CM) * sizeof(float);     // 158208 B
    cudaFuncSetAttribute(f_kernel, cudaFuncAttributeMaxDynamicSharedMemorySize, (int)smem3);
    cudaFuncSetAttribute(dwfuse_kernel, cudaFuncAttributeMaxDynamicSharedMemorySize, (int)smem4);

    pool_kernel<<<NB * CIN, 96>>>(x);
    gfilt_kernel<<<dim3(9, NB), CM>>>(conv_w, conv_b);
    f_kernel<<<dim3(36, NB), 256, smem3>>>(x, conv_w, conv_b);
    dwfuse_kernel<<<dim3(48, NB), 256, smem4>>>(dw_b, fuse_w, fuse_b, y);
}